// round 2
// baseline (speedup 1.0000x reference)
#include <cuda_runtime.h>
#include <cstdint>

#define T_SEQ 2048
#define BATCH 256
#define HID   64
#define INP   7

typedef unsigned long long ull;

__device__ __forceinline__ ull fma2(ull a, ull b, ull c) {
    ull d;
    asm("fma.rn.f32x2 %0, %1, %2, %3;" : "=l"(d) : "l"(a), "l"(b), "l"(c));
    return d;
}
__device__ __forceinline__ ull add2(ull a, ull b) {
    ull d;
    asm("add.rn.f32x2 %0, %1, %2;" : "=l"(d) : "l"(a), "l"(b));
    return d;
}
__device__ __forceinline__ ull pack2(float lo, float hi) {
    ull d; asm("mov.b64 %0, {%1, %2};" : "=l"(d) : "f"(lo), "f"(hi)); return d;
}
__device__ __forceinline__ float2 unpack2(ull a) {
    float2 r; asm("mov.b64 {%0, %1}, %2;" : "=f"(r.x), "=f"(r.y) : "l"(a)); return r;
}
__device__ __forceinline__ float htanh(float x) {
    float y; asm("tanh.approx.f32 %0, %1;" : "=f"(y) : "f"(x)); return y;
}

// grid = 128 CTAs x 512 threads; each CTA runs 2 independent batch chains
// (chain = tid/256), synchronized with per-chain NAMED barriers so the two
// chains free-run and mutually hide each other's serial tails.
//
// Within a chain, thread w in [0,256) owns gate-row r = (w&3)*64 + (w>>2)
// (gi = w&3 in PyTorch order i,f,g,o; unit u = w>>2). Per step it computes
// z_r = W_hh[r]·h + W_ih[r]·x + bias (packed f32x2 FMAs, weights in regs),
// applies the unified activation a = m*tanh(s*z)+b (HW MUFU.TANH;
// sigmoid(z) = 0.5*tanh(z/2)+0.5), and stores a at sh_a[4u+gi]. The gi==0
// lanes (one per unit, spread over all warps) then read their unit's 4 gates
// as one float4 and do c = f*c + i*g; h = o*tanh(c).
//
// Backward direction = ONE LSTM step on x[T-1] from zero state (scan[0] of
// the reversed sequence), fused as an epilogue with the final linear.
struct ChainSmem {
    float h[64];
    float a[256];
    float x[8];
    float hb[64];
};

__global__ void __launch_bounds__(512, 1)
bilstm_kernel(const float* __restrict__ x,      // [B,T,I]
              const float* __restrict__ Wih_f,  // [256,7]
              const float* __restrict__ Whh_f,  // [256,64]
              const float* __restrict__ bih_f,  // [256]
              const float* __restrict__ bhh_f,  // [256]
              const float* __restrict__ Wih_b,  // [256,7]
              const float* __restrict__ Whh_b,  // unused (h0 = 0 for single bwd step)
              const float* __restrict__ bih_b,  // [256]
              const float* __restrict__ bhh_b,  // [256]
              const float* __restrict__ Wlin,   // [3,128]
              const float* __restrict__ blin,   // [3]
              float* __restrict__ out)          // [B,3]
{
    __shared__ __align__(16) ChainSmem cs[2];

    const int tid   = threadIdx.x;
    const int chain = tid >> 8;          // 0 or 1
    const int w     = tid & 255;         // within-chain thread id
    const int gi    = w & 3;             // gate index (i,f,g,o)
    const int u     = w >> 2;            // hidden unit
    const int r     = gi * 64 + u;       // weight row in [4H, *] tensors
    const int b     = blockIdx.x * 2 + chain;
    const int barid = 1 + chain;
    ChainSmem& S = cs[chain];

    const float* xb = x + (size_t)b * T_SEQ * INP;

    // activation affine params: gi==2 -> tanh(z); else 0.5*tanh(0.5z)+0.5
    const float act_s = (gi == 2) ? 1.0f : 0.5f;
    const float act_m = (gi == 2) ? 1.0f : 0.5f;
    const float act_b = (gi == 2) ? 0.0f : 0.5f;

    // ---- one-time weight load into registers ----
    ull wrec[32];
    const ull* wrow = reinterpret_cast<const ull*>(Whh_f + r * HID);
#pragma unroll
    for (int m = 0; m < 32; m++) wrec[m] = wrow[m];

    float wih_s[8];
#pragma unroll
    for (int i = 0; i < INP; i++) wih_s[i] = Wih_f[r * INP + i];
    wih_s[7] = 0.0f;
    ull wih2[4];
#pragma unroll
    for (int m = 0; m < 4; m++) wih2[m] = pack2(wih_s[2 * m], wih_s[2 * m + 1]);

    const float bias = bih_f[r] + bhh_f[r];

    if (w < 64)  S.h[w] = 0.0f;
    if (w < INP) S.x[w] = xb[w];
    if (w == 7)  S.x[7] = 0.0f;
    float c = 0.0f;
    __syncthreads();   // one full-CTA sync for init only

    for (int t = 0; t < T_SEQ; t++) {
        // prefetch x[t+1]
        float xpre = 0.0f;
        if (w < INP && t + 1 < T_SEQ) xpre = __ldg(xb + (size_t)(t + 1) * INP + w);

        // z_r = W_hh[r]·h + W_ih[r]·x + bias
        ull acc0 = pack2(bias, 0.0f), acc1 = 0ull, acc2 = 0ull, acc3 = 0ull;
        const ulonglong2* h2 = reinterpret_cast<const ulonglong2*>(S.h);
#pragma unroll
        for (int m = 0; m < 8; m++) {
            ulonglong2 ha = h2[2 * m];
            ulonglong2 hb = h2[2 * m + 1];
            acc0 = fma2(wrec[4 * m + 0], ha.x, acc0);
            acc1 = fma2(wrec[4 * m + 1], ha.y, acc1);
            acc2 = fma2(wrec[4 * m + 2], hb.x, acc2);
            acc3 = fma2(wrec[4 * m + 3], hb.y, acc3);
        }
        {
            const ulonglong2* x2 = reinterpret_cast<const ulonglong2*>(S.x);
            ulonglong2 xv = x2[0];
            ulonglong2 xw = x2[1];
            acc0 = fma2(wih2[0], xv.x, acc0);
            acc1 = fma2(wih2[1], xv.y, acc1);
            acc2 = fma2(wih2[2], xw.x, acc2);
            acc3 = fma2(wih2[3], xw.y, acc3);
        }
        ull s2 = add2(add2(acc0, acc1), add2(acc2, acc3));
        float2 sf = unpack2(s2);
        float z = sf.x + sf.y;
        // unified activation via HW tanh
        S.a[w] = fmaf(act_m, htanh(act_s * z), act_b);
        asm volatile("bar.sync %0, 256;" :: "r"(barid) : "memory");

        // state update: gi==0 lanes own unit u
        if (gi == 0) {
            float4 g4 = reinterpret_cast<const float4*>(S.a)[u];  // {i,f,g,o}
            c = g4.y * c + g4.x * g4.z;
            S.h[u] = g4.w * htanh(c);
        }
        if (w < INP && t + 1 < T_SEQ) S.x[w] = xpre;
        asm volatile("bar.sync %0, 256;" :: "r"(barid) : "memory");
    }

    // ---- backward direction: ONE step on x[T-1] from zero state ----
    {
        float zb = bih_b[r] + bhh_b[r];
#pragma unroll
        for (int i = 0; i < INP; i++) zb += Wih_b[r * INP + i] * S.x[i];
        S.a[w] = fmaf(act_m, htanh(act_s * zb), act_b);
        asm volatile("bar.sync %0, 256;" :: "r"(barid) : "memory");
        if (gi == 0) {
            float4 g4 = reinterpret_cast<const float4*>(S.a)[u];
            float cb = g4.x * g4.z;            // f*c0 == 0
            S.hb[u] = g4.w * htanh(cb);
        }
        asm volatile("bar.sync %0, 256;" :: "r"(barid) : "memory");
    }

    // ---- final linear: out[b] = W_lin @ concat(h_f, h_b) + b_lin ----
    if (w < 3) {
        float a = blin[w];
#pragma unroll 16
        for (int k = 0; k < 64; k++) a += Wlin[w * 128 + k] * S.h[k];
#pragma unroll 16
        for (int k = 0; k < 64; k++) a += Wlin[w * 128 + 64 + k] * S.hb[k];
        out[b * 3 + w] = a;
    }
}

extern "C" void kernel_launch(void* const* d_in, const int* in_sizes, int n_in,
                              void* d_out, int out_size) {
    (void)in_sizes; (void)n_in; (void)out_size;
    bilstm_kernel<<<BATCH / 2, 512>>>(
        (const float*)d_in[0],  (const float*)d_in[1], (const float*)d_in[2],
        (const float*)d_in[3],  (const float*)d_in[4], (const float*)d_in[5],
        (const float*)d_in[6],  (const float*)d_in[7], (const float*)d_in[8],
        (const float*)d_in[9],  (const float*)d_in[10], (float*)d_out);
}